// round 3
// baseline (speedup 1.0000x reference)
#include <cuda_runtime.h>
#include <cuda_bf16.h>

// CopyMechanism: pointer-generator gate + vocab scale + scatter-add.
// B=16, T=128, H=512, V=32000, S=400.
//
// 3-kernel split (graph-captured in one stream, implicit ordering):
//   K1: p_gen per row -> __device__ scratch (warp-per-row reduction)
//   K2: pure streaming out = p_gen[row]*vocab (no barriers, max HBM)
//   K3: scatter atomics
//
// Inputs (metadata order):
//  0 context_vecs [B,T,H] f32,  1 hidden [B,T,H] f32,  2 trg_embs [B,T,H] f32
//  3 vocab_dists [B,T,V] f32,   4 attn_dists [B,T,S] f32, 5 src_ids [B,T,S] i32
//  6 pad_id (unused), 7 w_h [1,H], 8 w_s [1,H], 9 w_x_w [1,H], 10 w_x_b [1]
// output: [B,T,V] f32

#define HDIM   512
#define VDIM   32000
#define SDIM   400
#define NROWS  2048            // B*T
#define V4     (VDIM / 4)      // 8000 float4 per row
#define TOTAL4 ((long long)NROWS * V4)   // 16,384,000 float4

__device__ float g_pgen[NROWS];   // scratch: per-row gate

// ---------------- K1: gate -> p_gen ----------------
// One warp per row. 8 warps/block, 256 blocks.
__global__ __launch_bounds__(256)
void gate_kernel(const float* __restrict__ ctx,
                 const float* __restrict__ hid,
                 const float* __restrict__ trg,
                 const float* __restrict__ w_h,
                 const float* __restrict__ w_s,
                 const float* __restrict__ w_x,
                 const float* __restrict__ w_b)
{
    const int warp = (blockIdx.x * blockDim.x + threadIdx.x) >> 5;
    const int lane = threadIdx.x & 31;
    if (warp >= NROWS) return;

    const float4* c4 = reinterpret_cast<const float4*>(ctx + (size_t)warp * HDIM);
    const float4* h4 = reinterpret_cast<const float4*>(hid + (size_t)warp * HDIM);
    const float4* t4 = reinterpret_cast<const float4*>(trg + (size_t)warp * HDIM);
    const float4* wh4 = reinterpret_cast<const float4*>(w_h);
    const float4* ws4 = reinterpret_cast<const float4*>(w_s);
    const float4* wx4 = reinterpret_cast<const float4*>(w_x);

    float acc = 0.0f;
    #pragma unroll
    for (int i = 0; i < HDIM / 4 / 32; i++) {      // 4 iterations
        int idx = i * 32 + lane;
        float4 c = c4[idx], h = h4[idx], t = t4[idx];
        float4 a = wh4[idx], b = ws4[idx], x = wx4[idx];
        acc += c.x * a.x + c.y * a.y + c.z * a.z + c.w * a.w;
        acc += h.x * b.x + h.y * b.y + h.z * b.z + h.w * b.w;
        acc += t.x * x.x + t.y * x.y + t.z * x.z + t.w * x.w;
    }
    #pragma unroll
    for (int o = 16; o > 0; o >>= 1)
        acc += __shfl_down_sync(0xFFFFFFFFu, acc, o);
    if (lane == 0) {
        float logit = acc + w_b[0];
        g_pgen[warp] = 1.0f / (1.0f + __expf(-logit));
    }
}

// ---------------- K2: pure streaming scale ----------------
// Flat index over all float4 of [B*T, V]. row = idx / V4 (compiler -> mul-hi).
__global__ __launch_bounds__(256)
void scale_kernel(const float* __restrict__ vocab,
                  float* __restrict__ out)
{
    const long long stride = (long long)gridDim.x * blockDim.x;
    const float4* v4 = reinterpret_cast<const float4*>(vocab);
    float4* o4 = reinterpret_cast<float4*>(out);

    for (long long i = (long long)blockIdx.x * blockDim.x + threadIdx.x;
         i < TOTAL4; i += stride) {
        int row = (int)(i / V4);
        float p = __ldg(&g_pgen[row]);        // L1-hot (8 KB total)
        float4 v = __ldcs(&v4[i]);            // streaming read
        v.x *= p; v.y *= p; v.z *= p; v.w *= p;
        __stcs(&o4[i], v);                    // streaming write
    }
}

// ---------------- K3: scatter atomics ----------------
__global__ __launch_bounds__(256)
void scatter_kernel(const float* __restrict__ attn,
                    const int*   __restrict__ src_ids,
                    float* __restrict__ out)
{
    const int j = blockIdx.x * blockDim.x + threadIdx.x;
    if (j >= NROWS * SDIM) return;
    const int row = j / SDIM;
    const float p = __ldg(&g_pgen[row]);
    const float val = (1.0f - p) * attn[j];
    atomicAdd(out + (size_t)row * VDIM + src_ids[j], val);
}

extern "C" void kernel_launch(void* const* d_in, const int* in_sizes, int n_in,
                              void* d_out, int out_size) {
    const float* ctx   = (const float*)d_in[0];
    const float* hid   = (const float*)d_in[1];
    const float* trg   = (const float*)d_in[2];
    const float* vocab = (const float*)d_in[3];
    const float* attn  = (const float*)d_in[4];
    const int*   sid   = (const int*)d_in[5];
    const float* w_h   = (const float*)d_in[7];
    const float* w_s   = (const float*)d_in[8];
    const float* w_x   = (const float*)d_in[9];
    const float* w_b   = (const float*)d_in[10];
    float* out = (float*)d_out;

    // K1: 2048 warps = 256 blocks x 256 threads (8 warps each)
    gate_kernel<<<NROWS / 8, 256>>>(ctx, hid, trg, w_h, w_s, w_x, w_b);

    // K2: ~4 float4 per thread: 16.384M / (256*4) = 16000 blocks
    scale_kernel<<<16000, 256>>>(vocab, out);

    // K3: 819200 items
    scatter_kernel<<<(NROWS * SDIM + 255) / 256, 256>>>(attn, sid, out);
}

// round 6
// speedup vs baseline: 1.0003x; 1.0003x over previous
#include <cuda_runtime.h>
#include <cuda_bf16.h>

// CopyMechanism fused kernel (pointer-generator): gate + vocab scale + scatter.
// B=16, T=128, H=512, V=32000, S=400. One CTA per (b,t) row, 2048 CTAs.
//
// R3: fused (R1 base) + software-pipelined gate (vocab prefetch issued before
// the gate barrier), single-barrier reduction, __ldcs on read-once vocab.
//
// Inputs (metadata order):
//  0 context_vecs [B,T,H] f32,  1 hidden [B,T,H] f32,  2 trg_embs [B,T,H] f32
//  3 vocab_dists [B,T,V] f32,   4 attn_dists [B,T,S] f32, 5 src_ids [B,T,S] i32
//  6 pad_id (unused), 7 w_h [1,H], 8 w_s [1,H], 9 w_x_w [1,H], 10 w_x_b [1]
// output: [B,T,V] f32

#define HDIM 512
#define VDIM 32000
#define SDIM 400
#define NTHREADS 256
#define V4 (VDIM / 4)      // 8000 float4 per row
#define PF 4               // prefetch depth (float4 per thread)

__global__ __launch_bounds__(NTHREADS)
void copy_mechanism_kernel(
    const float* __restrict__ ctx,
    const float* __restrict__ hid,
    const float* __restrict__ trg,
    const float* __restrict__ vocab,
    const float* __restrict__ attn,
    const int*   __restrict__ src_ids,
    const float* __restrict__ w_h,
    const float* __restrict__ w_s,
    const float* __restrict__ w_x,
    const float* __restrict__ w_b,
    float* __restrict__ out)
{
    const int row  = blockIdx.x;        // 0 .. B*T-1
    const int tid  = threadIdx.x;
    const int lane = tid & 31;
    const int warp = tid >> 5;

    __shared__ float s_red[NTHREADS / 32];

    const float4* v4 = reinterpret_cast<const float4*>(vocab + (size_t)row * VDIM);
    float4*       o4 = reinterpret_cast<float4*>(out + (size_t)row * VDIM);

    // ---- Phase 0: prefetch first PF vocab chunks (streaming, read-once) ----
    // Issued before any gate work so DRAM streaming starts immediately.
    float4 pf[PF];
    #pragma unroll
    for (int k = 0; k < PF; k++)
        pf[k] = __ldcs(&v4[k * NTHREADS + tid]);

    // ---- Phase 1: gate logit = <ctx,w_h> + <hid,w_s> + <trg,w_x> + b ----
    float acc;
    {
        const float2* c2  = reinterpret_cast<const float2*>(ctx + (size_t)row * HDIM);
        const float2* h2  = reinterpret_cast<const float2*>(hid + (size_t)row * HDIM);
        const float2* t2  = reinterpret_cast<const float2*>(trg + (size_t)row * HDIM);
        const float2* wh2 = reinterpret_cast<const float2*>(w_h);
        const float2* ws2 = reinterpret_cast<const float2*>(w_s);
        const float2* wx2 = reinterpret_cast<const float2*>(w_x);

        // HDIM/2 = 256 float2 -> exactly one per thread
        float2 cv = c2[tid], hv = h2[tid], tv = t2[tid];
        float2 wh = wh2[tid], ws = ws2[tid], wx = wx2[tid];
        acc = cv.x * wh.x + cv.y * wh.y
            + hv.x * ws.x + hv.y * ws.y
            + tv.x * wx.x + tv.y * wx.y;

        #pragma unroll
        for (int o = 16; o > 0; o >>= 1)
            acc += __shfl_down_sync(0xFFFFFFFFu, acc, o);
        if (lane == 0) s_red[warp] = acc;
    }
    const float bias = w_b[0];
    __syncthreads();   // single barrier: warp sums visible

    // Redundant final combine in every thread (no second barrier needed).
    float logit = bias;
    #pragma unroll
    for (int w = 0; w < NTHREADS / 32; w++) logit += s_red[w];
    const float p_gen     = 1.0f / (1.0f + __expf(-logit));
    const float one_minus = 1.0f - p_gen;

    // ---- Phase 2a: consume prefetched chunks ----
    #pragma unroll
    for (int k = 0; k < PF; k++) {
        float4 v = pf[k];
        v.x *= p_gen; v.y *= p_gen; v.z *= p_gen; v.w *= p_gen;
        o4[k * NTHREADS + tid] = v;
    }

    // ---- Phase 2b: remaining streaming scale ----
    #pragma unroll 4
    for (int i = PF * NTHREADS + tid; i < V4; i += NTHREADS) {
        float4 v = __ldcs(&v4[i]);
        v.x *= p_gen; v.y *= p_gen; v.z *= p_gen; v.w *= p_gen;
        o4[i] = v;
    }

    __syncthreads();   // row fully written before scatter RMW

    // ---- Phase 3: scatter-add (1-p_gen)*attn into this row ----
    {
        const float* a   = attn + (size_t)row * SDIM;
        const int*   ids = src_ids + (size_t)row * SDIM;
        float* orow = out + (size_t)row * VDIM;
        for (int j = tid; j < SDIM; j += NTHREADS)
            atomicAdd(&orow[ids[j]], one_minus * a[j]);
    }
}

extern "C" void kernel_launch(void* const* d_in, const int* in_sizes, int n_in,
                              void* d_out, int out_size) {
    const float* ctx   = (const float*)d_in[0];
    const float* hid   = (const float*)d_in[1];
    const float* trg   = (const float*)d_in[2];
    const float* vocab = (const float*)d_in[3];
    const float* attn  = (const float*)d_in[4];
    const int*   sid   = (const int*)d_in[5];
    const float* w_h   = (const float*)d_in[7];
    const float* w_s   = (const float*)d_in[8];
    const float* w_x   = (const float*)d_in[9];
    const float* w_b   = (const float*)d_in[10];
    float* out = (float*)d_out;

    const int rows = in_sizes[0] / HDIM;  // B*T = 2048
    copy_mechanism_kernel<<<rows, NTHREADS>>>(
        ctx, hid, trg, vocab, attn, sid, w_h, w_s, w_x, w_b, out);
}

// round 8
// speedup vs baseline: 1.1998x; 1.1994x over previous
#include <cuda_runtime.h>
#include <cuda_bf16.h>

// CopyMechanism fused kernel (pointer-generator): gate + vocab scale + scatter.
// B=16, T=128, H=512, V=32000, S=400.
//
// R4: quarter-row tiling (8192 CTAs, 6.9 waves) to kill wave-quantization and
// drain-tail losses of the 1-CTA-per-row layout (1.73 waves). Scatter is
// range-filtered per tile so each CTA only atomics into the quarter it wrote
// itself (no cross-CTA ordering needed). Gate recomputed per tile (L2-hit
// redundant reads, zero extra DRAM).
//
// Inputs (metadata order):
//  0 context_vecs [B,T,H] f32,  1 hidden [B,T,H] f32,  2 trg_embs [B,T,H] f32
//  3 vocab_dists [B,T,V] f32,   4 attn_dists [B,T,S] f32, 5 src_ids [B,T,S] i32
//  6 pad_id (unused), 7 w_h [1,H], 8 w_s [1,H], 9 w_x_w [1,H], 10 w_x_b [1]
// output: [B,T,V] f32

#define HDIM 512
#define VDIM 32000
#define SDIM 400
#define NTHREADS 256
#define TILES_PER_ROW 4
#define TILE_ELEMS (VDIM / TILES_PER_ROW)   // 8000 floats
#define TILE4 (TILE_ELEMS / 4)              // 2000 float4

__global__ __launch_bounds__(NTHREADS)
void copy_mechanism_kernel(
    const float* __restrict__ ctx,
    const float* __restrict__ hid,
    const float* __restrict__ trg,
    const float* __restrict__ vocab,
    const float* __restrict__ attn,
    const int*   __restrict__ src_ids,
    const float* __restrict__ w_h,
    const float* __restrict__ w_s,
    const float* __restrict__ w_x,
    const float* __restrict__ w_b,
    float* __restrict__ out)
{
    const int row  = blockIdx.x >> 2;       // 0 .. B*T-1
    const int quad = blockIdx.x & 3;        // which quarter of the row
    const int tid  = threadIdx.x;
    const int lane = tid & 31;
    const int warp = tid >> 5;

    __shared__ float s_red[NTHREADS / 32];
    __shared__ float s_pgen;

    // ---- Phase 1: gate logit = <ctx,w_h> + <hid,w_s> + <trg,w_x> + b ----
    // Redundant across the 4 tiles of a row; lines are L2-hot.
    {
        const float2* c2  = reinterpret_cast<const float2*>(ctx + (size_t)row * HDIM);
        const float2* h2  = reinterpret_cast<const float2*>(hid + (size_t)row * HDIM);
        const float2* t2  = reinterpret_cast<const float2*>(trg + (size_t)row * HDIM);
        const float2* wh2 = reinterpret_cast<const float2*>(w_h);
        const float2* ws2 = reinterpret_cast<const float2*>(w_s);
        const float2* wx2 = reinterpret_cast<const float2*>(w_x);

        // HDIM/2 = 256 float2 -> exactly one per thread
        float2 cv = c2[tid], hv = h2[tid], tv = t2[tid];
        float2 wh = wh2[tid], ws = ws2[tid], wx = wx2[tid];
        float acc = cv.x * wh.x + cv.y * wh.y
                  + hv.x * ws.x + hv.y * ws.y
                  + tv.x * wx.x + tv.y * wx.y;

        #pragma unroll
        for (int o = 16; o > 0; o >>= 1)
            acc += __shfl_down_sync(0xFFFFFFFFu, acc, o);
        if (lane == 0) s_red[warp] = acc;
        __syncthreads();
        if (warp == 0) {
            float v = (lane < NTHREADS / 32) ? s_red[lane] : 0.0f;
            #pragma unroll
            for (int o = 4; o > 0; o >>= 1)
                v += __shfl_down_sync(0xFFFFFFFFu, v, o);
            if (lane == 0) {
                float logit = v + w_b[0];
                s_pgen = 1.0f / (1.0f + __expf(-logit));
            }
        }
        __syncthreads();
    }

    const float p_gen     = s_pgen;
    const float one_minus = 1.0f - p_gen;

    // ---- Phase 2: out = p_gen * vocab over this tile (float4 stream) ----
    {
        const float4* v4 = reinterpret_cast<const float4*>(vocab + (size_t)row * VDIM)
                         + quad * TILE4;
        float4* o4 = reinterpret_cast<float4*>(out + (size_t)row * VDIM)
                   + quad * TILE4;
        #pragma unroll 4
        for (int i = tid; i < TILE4; i += NTHREADS) {
            float4 v = v4[i];
            v.x *= p_gen; v.y *= p_gen; v.z *= p_gen; v.w *= p_gen;
            o4[i] = v;
        }
    }

    __syncthreads();   // tile fully written before scatter RMW into it

    // ---- Phase 3: range-filtered scatter-add into THIS tile only ----
    // Scan all S entries of the row; only ids inside [lo, hi) belong to the
    // region this CTA wrote, so no cross-CTA ordering is needed.
    {
        const int lo = quad * TILE_ELEMS;
        const int hi = lo + TILE_ELEMS;
        const float* a   = attn + (size_t)row * SDIM;
        const int*   ids = src_ids + (size_t)row * SDIM;
        float* orow = out + (size_t)row * VDIM;
        for (int j = tid; j < SDIM; j += NTHREADS) {
            int id = ids[j];
            if (id >= lo && id < hi)
                atomicAdd(&orow[id], one_minus * a[j]);
        }
    }
}

extern "C" void kernel_launch(void* const* d_in, const int* in_sizes, int n_in,
                              void* d_out, int out_size) {
    const float* ctx   = (const float*)d_in[0];
    const float* hid   = (const float*)d_in[1];
    const float* trg   = (const float*)d_in[2];
    const float* vocab = (const float*)d_in[3];
    const float* attn  = (const float*)d_in[4];
    const int*   sid   = (const int*)d_in[5];
    const float* w_h   = (const float*)d_in[7];
    const float* w_s   = (const float*)d_in[8];
    const float* w_x   = (const float*)d_in[9];
    const float* w_b   = (const float*)d_in[10];
    float* out = (float*)d_out;

    const int rows = in_sizes[0] / HDIM;  // B*T = 2048
    copy_mechanism_kernel<<<rows * TILES_PER_ROW, NTHREADS>>>(
        ctx, hid, trg, vocab, attn, sid, w_h, w_s, w_x, w_b, out);
}